// round 14
// baseline (speedup 1.0000x reference)
#include <cuda_runtime.h>
#include <cuda_bf16.h>

// AxialAttention via mma.sync.m16n8k16 bf16 with 2-term bf16 split (3 MMAs per tile).
// R10: weights pre-packed into per-fragment uint4 layout -> 1 LDG.128 per B-tile,
// no smem weight staging, 2 barriers/head, Q pre-scaled by 0.25.

typedef unsigned int uint32;

#define NHEADS 8

// fragment-packed split weights: each uint4 = {bh0, bh1, bl0, bl1} for one lane of one B-tile
__device__ __align__(16) uint4 g_Wqkv4[2][NHEADS][6][8][32]; // [pass][h][nt][kt][lane]
__device__ __align__(16) uint4 g_Wo4[2][NHEADS][16][32];     // [pass][h][nt][lane]

__device__ __forceinline__ float trunc_bf16(float x) {
    return __uint_as_float(__float_as_uint(x) & 0xffff0000u);
}
// pack (e0 -> low half, e1 -> high half); h = hi parts, l = residuals
__device__ __forceinline__ void split_pack(float e0, float e1, uint32& h, uint32& l) {
    float h0 = trunc_bf16(e0), h1 = trunc_bf16(e1);
    asm("cvt.rn.bf16x2.f32 %0, %1, %2;" : "=r"(h) : "f"(h1), "f"(h0));
    asm("cvt.rn.bf16x2.f32 %0, %1, %2;" : "=r"(l) : "f"(e1 - h1), "f"(e0 - h0));
}

__device__ __forceinline__ void mma16816(float* c, const uint32* a, const uint32* b) {
    asm volatile("mma.sync.aligned.m16n8k16.row.col.f32.bf16.bf16.f32 "
                 "{%0,%1,%2,%3}, {%4,%5,%6,%7}, {%8,%9}, {%0,%1,%2,%3};"
                 : "+f"(c[0]), "+f"(c[1]), "+f"(c[2]), "+f"(c[3])
                 : "r"(a[0]), "r"(a[1]), "r"(a[2]), "r"(a[3]), "r"(b[0]), "r"(b[1]));
}

// ---------------- setup: split weights into fragment-packed hi/lo scratch ----------------
__global__ void split_weights_kernel(const float* __restrict__ Wq0, const float* __restrict__ Wkv0,
                                     const float* __restrict__ Wo0,
                                     const float* __restrict__ Wq1, const float* __restrict__ Wkv1,
                                     const float* __restrict__ Wo1)
{
    int idx = blockIdx.x * blockDim.x + threadIdx.x;

    // QKV frags: [p][h][nt(6)][kt(8)][lane(32)] = 49152 entries
    if (idx < 2 * NHEADS * 6 * 8 * 32) {
        int ln = idx & 31;
        int kt = (idx >> 5) & 7;
        int nt = (idx >> 8) % 6;
        int h  = (idx / (32 * 8 * 6)) & 7;
        int p  = idx / (32 * 8 * 6 * NHEADS);
        int g  = ln >> 2, t4 = ln & 3;
        int n  = 8 * nt + g;
        int k0 = kt * 16 + t4 * 2;
        const float* Wq  = p ? Wq1  : Wq0;
        const float* Wkv = p ? Wkv1 : Wkv0;
        float v[4];
#pragma unroll
        for (int j = 0; j < 4; ++j) {
            int k = k0 + (j >> 1) * 8 + (j & 1);
            if (n < 16)      v[j] = Wq [k * 128 + h * 16 + n];
            else if (n < 32) v[j] = Wkv[k * 256 + h * 16 + (n - 16)];
            else             v[j] = Wkv[k * 256 + 128 + h * 16 + (n - 32)];
        }
        uint4 r;
        split_pack(v[0], v[1], r.x, r.z);
        split_pack(v[2], v[3], r.y, r.w);
        reinterpret_cast<uint4*>(g_Wqkv4)[idx] = r;
    }

    // Wo frags: [p][h][nt(16)][lane(32)] = 8192 entries
    if (idx < 2 * NHEADS * 16 * 32) {
        int ln = idx & 31;
        int nt = (idx >> 5) & 15;
        int h  = (idx >> 9) & 7;
        int p  = idx >> 12;
        int g  = ln >> 2, t4 = ln & 3;
        int n  = 8 * nt + g;
        int e0 = t4 * 2;
        const float* Wo = p ? Wo1 : Wo0;
        float v0 = Wo[(h * 16 + e0)     * 128 + n];
        float v1 = Wo[(h * 16 + e0 + 1) * 128 + n];
        float v2 = Wo[(h * 16 + e0 + 8) * 128 + n];
        float v3 = Wo[(h * 16 + e0 + 9) * 128 + n];
        uint4 r;
        split_pack(v0, v1, r.x, r.z);
        split_pack(v2, v3, r.y, r.w);
        reinterpret_cast<uint4*>(g_Wo4)[idx] = r;
    }
}

// ---------------- main fused kernel ----------------
// smem layout strides (halves)
#define XS 136   // sX [128 t][136]
#define KS 24    // sK [128 j][24]
#define VS 136   // sV [16 e][136]

template <int PASS>
__launch_bounds__(256)
__global__ void axial_mma_kernel(const float* __restrict__ x,
                                 const float* __restrict__ bo,
                                 float* __restrict__ out)
{
    extern __shared__ __nv_bfloat16 sm[];
    __nv_bfloat16* sXhi = sm;
    __nv_bfloat16* sXlo = sXhi + 128 * XS;
    __nv_bfloat16* sKhi = sXlo + 128 * XS;
    __nv_bfloat16* sKlo = sKhi + 128 * KS;
    __nv_bfloat16* sVhi = sKlo + 128 * KS;
    __nv_bfloat16* sVlo = sVhi + 16 * VS;

    const int tid = threadIdx.x;
    const int w   = tid >> 5;        // warp 0..7
    const int ln  = tid & 31;
    const int g   = ln >> 2;         // group row 0..7
    const int t4  = ln & 3;
    const int s   = blockIdx.x;

    long base;
    int  tstride;
    if (PASS == 0) { base = (long)(s >> 7) * 2097152 + (long)(s & 127) * 128; tstride = 16384; }
    else           { base = (long)s * 16384;                                  tstride = 128;   }

    // ---- load X, split to bf16 hi/lo in smem [t][d] ----
    for (int i = tid; i < 128 * 32; i += 256) {
        int t = i >> 5, c = (i & 31) << 2;
        float4 v = *reinterpret_cast<const float4*>(x + base + (long)t * tstride + c);
        uint32 h0, l0, h1, l1;
        split_pack(v.x, v.y, h0, l0);
        split_pack(v.z, v.w, h1, l1);
        *reinterpret_cast<uint32*>(&sXhi[t * XS + c])     = h0;
        *reinterpret_cast<uint32*>(&sXhi[t * XS + c + 2]) = h1;
        *reinterpret_cast<uint32*>(&sXlo[t * XS + c])     = l0;
        *reinterpret_cast<uint32*>(&sXlo[t * XS + c + 2]) = l1;
    }
    __syncthreads();   // X ready for all warps

    float accD[16][4];
#pragma unroll
    for (int i = 0; i < 16; ++i)
#pragma unroll
        for (int j = 0; j < 4; ++j) accD[i][j] = 0.0f;

#pragma unroll 1
    for (int h = 0; h < NHEADS; ++h) {
        // ---- A: QKV = X @ Wqkv_head  (rows 16w..+16, 48 cols = 6 n-tiles) ----
        float qkv[6][4];
#pragma unroll
        for (int i = 0; i < 6; ++i)
#pragma unroll
            for (int j = 0; j < 4; ++j) qkv[i][j] = 0.0f;

#pragma unroll 1
        for (int kt = 0; kt < 8; ++kt) {
            uint32 ah[4], al[4];
            int xb = (16 * w + g) * XS + kt * 16 + t4 * 2;
            ah[0] = *reinterpret_cast<uint32*>(&sXhi[xb]);
            ah[1] = *reinterpret_cast<uint32*>(&sXhi[xb + 8 * XS]);
            ah[2] = *reinterpret_cast<uint32*>(&sXhi[xb + 8]);
            ah[3] = *reinterpret_cast<uint32*>(&sXhi[xb + 8 * XS + 8]);
            al[0] = *reinterpret_cast<uint32*>(&sXlo[xb]);
            al[1] = *reinterpret_cast<uint32*>(&sXlo[xb + 8 * XS]);
            al[2] = *reinterpret_cast<uint32*>(&sXlo[xb + 8]);
            al[3] = *reinterpret_cast<uint32*>(&sXlo[xb + 8 * XS + 8]);
#pragma unroll
            for (int nt = 0; nt < 6; ++nt) {
                uint4 wv = g_Wqkv4[PASS][h][nt][kt][ln];
                uint32 bh[2] = {wv.x, wv.y};
                uint32 bl[2] = {wv.z, wv.w};
                mma16816(qkv[nt], ah, bh);
                mma16816(qkv[nt], ah, bl);
                mma16816(qkv[nt], al, bh);
            }
        }

        // pre-scale Q by softmax scale (exact: power of two)
#pragma unroll
        for (int j = 0; j < 4; ++j) { qkv[0][j] *= 0.25f; qkv[1][j] *= 0.25f; }

        // ---- Q: C-frags -> A-frags directly (no smem) ----
        uint32 qh[4], ql[4];
        split_pack(qkv[0][0], qkv[0][1], qh[0], ql[0]);
        split_pack(qkv[0][2], qkv[0][3], qh[1], ql[1]);
        split_pack(qkv[1][0], qkv[1][1], qh[2], ql[2]);
        split_pack(qkv[1][2], qkv[1][3], qh[3], ql[3]);

        __syncthreads();   // all warps done reading sK/sV of previous head

        // ---- K -> sK[j][e] (B operand for S), packed pair stores ----
#pragma unroll
        for (int tk = 0; tk < 2; ++tk) {
            uint32 h0, l0, h1, l1;
            split_pack(qkv[2 + tk][0], qkv[2 + tk][1], h0, l0);
            split_pack(qkv[2 + tk][2], qkv[2 + tk][3], h1, l1);
            int kb = (16 * w + g) * KS + tk * 8 + t4 * 2;
            *reinterpret_cast<uint32*>(&sKhi[kb])          = h0;
            *reinterpret_cast<uint32*>(&sKhi[kb + 8 * KS]) = h1;
            *reinterpret_cast<uint32*>(&sKlo[kb])          = l0;
            *reinterpret_cast<uint32*>(&sKlo[kb + 8 * KS]) = l1;
        }
        // ---- V -> sV[e][j] (B operand for O), scalar stores ----
#pragma unroll
        for (int tv = 0; tv < 2; ++tv) {
            int e0 = tv * 8 + t4 * 2;
            int j0 = 16 * w + g;
            float c0 = qkv[4 + tv][0], c1 = qkv[4 + tv][1];
            float c2 = qkv[4 + tv][2], c3 = qkv[4 + tv][3];
            float hv;
            hv = trunc_bf16(c0); sVhi[e0 * VS + j0] = __float2bfloat16(hv);
            sVlo[e0 * VS + j0] = __float2bfloat16(c0 - hv);
            hv = trunc_bf16(c1); sVhi[(e0 + 1) * VS + j0] = __float2bfloat16(hv);
            sVlo[(e0 + 1) * VS + j0] = __float2bfloat16(c1 - hv);
            hv = trunc_bf16(c2); sVhi[e0 * VS + j0 + 8] = __float2bfloat16(hv);
            sVlo[e0 * VS + j0 + 8] = __float2bfloat16(c2 - hv);
            hv = trunc_bf16(c3); sVhi[(e0 + 1) * VS + j0 + 8] = __float2bfloat16(hv);
            sVlo[(e0 + 1) * VS + j0 + 8] = __float2bfloat16(c3 - hv);
        }
        __syncthreads();   // K/V published

        // ---- B: S = Q @ K^T  (16 n-tiles over j, K-dim = 16; Q already scaled) ----
        float S[16][4];
#pragma unroll
        for (int nt = 0; nt < 16; ++nt) {
#pragma unroll
            for (int j = 0; j < 4; ++j) S[nt][j] = 0.0f;
            int kb = (8 * nt + g) * KS + t4 * 2;
            uint32 bh[2], bl[2];
            bh[0] = *reinterpret_cast<uint32*>(&sKhi[kb]);
            bh[1] = *reinterpret_cast<uint32*>(&sKhi[kb + 8]);
            bl[0] = *reinterpret_cast<uint32*>(&sKlo[kb]);
            bl[1] = *reinterpret_cast<uint32*>(&sKlo[kb + 8]);
            mma16816(S[nt], qh, bh);
            mma16816(S[nt], qh, bl);
            mma16816(S[nt], ql, bh);
        }

        // ---- softmax over j (rows g and g+8 of this warp's 16) ----
        float mA = -1e30f, mB = -1e30f;
#pragma unroll
        for (int nt = 0; nt < 16; ++nt) {
            mA = fmaxf(mA, fmaxf(S[nt][0], S[nt][1]));
            mB = fmaxf(mB, fmaxf(S[nt][2], S[nt][3]));
        }
        mA = fmaxf(mA, __shfl_xor_sync(0xffffffffu, mA, 1));
        mA = fmaxf(mA, __shfl_xor_sync(0xffffffffu, mA, 2));
        mB = fmaxf(mB, __shfl_xor_sync(0xffffffffu, mB, 1));
        mB = fmaxf(mB, __shfl_xor_sync(0xffffffffu, mB, 2));
        float sA = 0.0f, sB = 0.0f;
#pragma unroll
        for (int nt = 0; nt < 16; ++nt) {
            S[nt][0] = __expf(S[nt][0] - mA); sA += S[nt][0];
            S[nt][1] = __expf(S[nt][1] - mA); sA += S[nt][1];
            S[nt][2] = __expf(S[nt][2] - mB); sB += S[nt][2];
            S[nt][3] = __expf(S[nt][3] - mB); sB += S[nt][3];
        }
        sA += __shfl_xor_sync(0xffffffffu, sA, 1);
        sA += __shfl_xor_sync(0xffffffffu, sA, 2);
        sB += __shfl_xor_sync(0xffffffffu, sB, 1);
        sB += __shfl_xor_sync(0xffffffffu, sB, 2);
        float iA = 1.0f / sA, iB = 1.0f / sB;
#pragma unroll
        for (int nt = 0; nt < 16; ++nt) {
            S[nt][0] *= iA; S[nt][1] *= iA; S[nt][2] *= iB; S[nt][3] *= iB;
        }

        // ---- C: O = P @ V  (P from S regs -> A-frags, V from sV[e][j]) ----
        float o[2][4];
#pragma unroll
        for (int i = 0; i < 2; ++i)
#pragma unroll
            for (int j = 0; j < 4; ++j) o[i][j] = 0.0f;
#pragma unroll
        for (int kt = 0; kt < 8; ++kt) {
            uint32 ph[4], pl[4];
            split_pack(S[2 * kt][0],     S[2 * kt][1],     ph[0], pl[0]);
            split_pack(S[2 * kt][2],     S[2 * kt][3],     ph[1], pl[1]);
            split_pack(S[2 * kt + 1][0], S[2 * kt + 1][1], ph[2], pl[2]);
            split_pack(S[2 * kt + 1][2], S[2 * kt + 1][3], ph[3], pl[3]);
#pragma unroll
            for (int nt = 0; nt < 2; ++nt) {
                int vb = (8 * nt + g) * VS + kt * 16 + t4 * 2;
                uint32 bh[2], bl[2];
                bh[0] = *reinterpret_cast<uint32*>(&sVhi[vb]);
                bh[1] = *reinterpret_cast<uint32*>(&sVhi[vb + 8]);
                bl[0] = *reinterpret_cast<uint32*>(&sVlo[vb]);
                bl[1] = *reinterpret_cast<uint32*>(&sVlo[vb + 8]);
                mma16816(o[nt], ph, bh);
                mma16816(o[nt], ph, bl);
                mma16816(o[nt], pl, bh);
            }
        }

        // ---- D: accD += O @ Wo_head  (O frags direct, K-dim = 16) ----
        uint32 oh[4], ol[4];
        split_pack(o[0][0], o[0][1], oh[0], ol[0]);
        split_pack(o[0][2], o[0][3], oh[1], ol[1]);
        split_pack(o[1][0], o[1][1], oh[2], ol[2]);
        split_pack(o[1][2], o[1][3], oh[3], ol[3]);
#pragma unroll
        for (int nt = 0; nt < 16; ++nt) {
            uint4 wv = g_Wo4[PASS][h][nt][ln];
            uint32 bh[2] = {wv.x, wv.y};
            uint32 bl[2] = {wv.z, wv.w};
            mma16816(accD[nt], oh, bh);
            mma16816(accD[nt], oh, bl);
            mma16816(accD[nt], ol, bh);
        }
    }

    // ---- epilogue: + bias; write (pass 0) or RMW (pass 1) ----
    int row0 = 16 * w + g;
#pragma unroll
    for (int nt = 0; nt < 16; ++nt) {
        int col = 8 * nt + t4 * 2;
        float2 b = *reinterpret_cast<const float2*>(&bo[col]);
        long o0 = base + (long)row0 * tstride + col;
        long o1 = base + (long)(row0 + 8) * tstride + col;
        float2 v0, v1;
        v0.x = accD[nt][0] + b.x; v0.y = accD[nt][1] + b.y;
        v1.x = accD[nt][2] + b.x; v1.y = accD[nt][3] + b.y;
        if (PASS == 1) {
            float2 p0 = *reinterpret_cast<const float2*>(&out[o0]);
            float2 p1 = *reinterpret_cast<const float2*>(&out[o1]);
            v0.x += p0.x; v0.y += p0.y;
            v1.x += p1.x; v1.y += p1.y;
        }
        *reinterpret_cast<float2*>(&out[o0]) = v0;
        *reinterpret_cast<float2*>(&out[o1]) = v1;
    }
}

extern "C" void kernel_launch(void* const* d_in, const int* in_sizes, int n_in,
                              void* d_out, int out_size)
{
    const float* x    = (const float*)d_in[0];
    const float* Wq0  = (const float*)d_in[1];
    const float* Wkv0 = (const float*)d_in[2];
    const float* Wo0  = (const float*)d_in[3];
    const float* bo0  = (const float*)d_in[4];
    const float* Wq1  = (const float*)d_in[5];
    const float* Wkv1 = (const float*)d_in[6];
    const float* Wo1  = (const float*)d_in[7];
    const float* bo1  = (const float*)d_in[8];
    float* out = (float*)d_out;

    const int smem_halves = 2 * 128 * XS + 2 * 128 * KS + 2 * 16 * VS;
    const int smem_bytes = smem_halves * 2;   // 90,624 B

    cudaFuncSetAttribute(axial_mma_kernel<0>,
                         cudaFuncAttributeMaxDynamicSharedMemorySize, smem_bytes);
    cudaFuncSetAttribute(axial_mma_kernel<1>,
                         cudaFuncAttributeMaxDynamicSharedMemorySize, smem_bytes);

    split_weights_kernel<<<192, 256>>>(Wq0, Wkv0, Wo0, Wq1, Wkv1, Wo1);
    axial_mma_kernel<0><<<1024, 256, smem_bytes>>>(x, bo0, out);
    axial_mma_kernel<1><<<1024, 256, smem_bytes>>>(x, bo1, out);
}